// round 6
// baseline (speedup 1.0000x reference)
#include <cuda_runtime.h>
#include <stdint.h>
#include <math.h>

#define BD    4
#define NSEQ  1024
#define DM    256
#define NH    8
#define HD    32
#define DFFN  1024
#define MROWS (BD * NSEQ)   // 4096
#define NQKV  768

// ---------------- static scratch ----------------
__device__ float g_qkin[MROWS * DM];        // embed + query_pos
__device__ float g_qkv[MROWS * NQKV];       // [4096, 768]: q | k | v
__device__ float g_tau[BD * NH * NSEQ];     // [B, H, N]
__device__ float g_ctx[MROWS * DM];
__device__ float g_y[MROWS * DM];
__device__ float g_x[MROWS * DM];
__device__ float g_h[MROWS * DFFN];

// ---------------- helpers ----------------
__device__ __forceinline__ unsigned f2tf(float f)
{
    unsigned u;
    asm("cvt.rna.tf32.f32 %0, %1;" : "=r"(u) : "f"(f));
    return u;
}

__device__ __forceinline__ void cp16(float* dst, const float* src)
{
    unsigned d = (unsigned)__cvta_generic_to_shared(dst);
    asm volatile("cp.async.cg.shared.global [%0], [%1], 16;" :: "r"(d), "l"(src));
}

#define CP_COMMIT() asm volatile("cp.async.commit_group;")

#define MMA_TF32(d, a, b0, b1)                                              \
    asm volatile("mma.sync.aligned.m16n8k8.row.col.f32.tf32.tf32.f32 "      \
                 "{%0,%1,%2,%3}, {%4,%5,%6,%7}, {%8,%9}, {%0,%1,%2,%3};"    \
                 : "+f"((d)[0]), "+f"((d)[1]), "+f"((d)[2]), "+f"((d)[3])   \
                 : "r"((a)[0]), "r"((a)[1]), "r"((a)[2]), "r"((a)[3]),      \
                   "r"(b0), "r"(b1))

// ---------------- elementwise: qk = embed + query_pos ----------------
__global__ void add_pos_kernel(const float4* __restrict__ a,
                               const float4* __restrict__ b,
                               float4* __restrict__ o)
{
    int i = blockIdx.x * blockDim.x + threadIdx.x;
    float4 x = a[i], y = b[i];
    o[i] = make_float4(x.x + y.x, x.y + y.y, x.z + y.z, x.w + y.w);
}

// ---------------- tau ----------------
__global__ void tau_kernel(const float* __restrict__ embed,
                           const float* __restrict__ tw,
                           const float* __restrict__ tb,
                           float* __restrict__ tau)
{
    int warp_id = (blockIdx.x * blockDim.x + threadIdx.x) >> 5;
    int lane = threadIdx.x & 31;
    const float* er = embed + (size_t)warp_id * DM;
    float ph[NH];
    #pragma unroll
    for (int h = 0; h < NH; h++) ph[h] = 0.f;
    #pragma unroll
    for (int t = 0; t < 8; t++) {
        int d = lane + t * 32;
        float e = er[d];
        #pragma unroll
        for (int h = 0; h < NH; h++) ph[h] += e * tw[h * DM + d];
    }
    #pragma unroll
    for (int h = 0; h < NH; h++) {
        float v = ph[h];
        #pragma unroll
        for (int o = 16; o > 0; o >>= 1) v += __shfl_xor_sync(0xffffffffu, v, o);
        if (lane == 0) {
            int b = warp_id >> 10, n = warp_id & 1023;
            tau[((size_t)b * NH + h) * NSEQ + n] = v + tb[h];
        }
    }
}

// ---------------- async tile loader for GEMM ----------------
template<int BM>
__device__ __forceinline__ void gemm_load(const float* __restrict__ Ag,
                                          const float* __restrict__ Wg,
                                          float* sA, float* sB, int tid, int K)
{
    constexpr int T = BM * 2;
    #pragma unroll
    for (int i = 0; i < (BM * 8) / T; i++) {
        int idx = tid + i * T;
        int row = idx >> 3, c4 = (idx & 7) << 2;
        cp16(sA + row * 36 + c4, Ag + (size_t)row * K + c4);
    }
    #pragma unroll
    for (int i = 0; i < 512 / T; i++) {
        int idx = tid + i * T;
        int row = idx >> 3, c4 = (idx & 7) << 2;
        cp16(sB + row * 36 + c4, Wg + (size_t)row * K + c4);
    }
    CP_COMMIT();
}

// ---------------- tf32 tensor-core GEMM (double-buffered cp.async) ----------------
template<int BM>
__global__ void gemm_tc(const float* __restrict__ A, const float* __restrict__ A2,
                        const float* __restrict__ W, const float* __restrict__ bias,
                        const float* __restrict__ resid, float* __restrict__ C,
                        int M, int N, int K, int doRelu, int nsplit)
{
    extern __shared__ float smem[];
    constexpr int STAGE = (BM + 64) * 36;
    int tid = threadIdx.x, lane = tid & 31, wid = tid >> 5;
    int m0 = blockIdx.y * BM, n0 = blockIdx.x * 64;
    const float* Ause = (n0 >= nsplit) ? A2 : A;
    const float* Abase = Ause + (size_t)m0 * K;
    const float* Wbase = W + (size_t)n0 * K;
    int nk = K >> 5;

    constexpr int WMN = BM / 32;
    int wm = (wid % WMN) * 32, wn = (wid / WMN) * 32;
    int gr = lane >> 2, gq = lane & 3;

    gemm_load<BM>(Abase, Wbase, smem, smem + BM * 36, tid, K);

    float acc[2][4][4];
    #pragma unroll
    for (int mi = 0; mi < 2; mi++)
        #pragma unroll
        for (int ni = 0; ni < 4; ni++)
            #pragma unroll
            for (int k = 0; k < 4; k++) acc[mi][ni][k] = 0.f;

    for (int kt = 0; kt < nk; kt++) {
        float* cur = smem + (kt & 1) * STAGE;
        float* nxt = smem + ((kt + 1) & 1) * STAGE;
        if (kt + 1 < nk) {
            gemm_load<BM>(Abase + (kt + 1) * 32, Wbase + (kt + 1) * 32,
                          nxt, nxt + BM * 36, tid, K);
            asm volatile("cp.async.wait_group 1;");
        } else {
            asm volatile("cp.async.wait_group 0;");
        }
        __syncthreads();
        const float* cA = cur;
        const float* cB = cur + BM * 36;
        #pragma unroll
        for (int k0 = 0; k0 < 32; k0 += 8) {
            unsigned af[2][4], bf[4][2];
            #pragma unroll
            for (int mi = 0; mi < 2; mi++) {
                int r = wm + mi * 16 + gr, c = k0 + gq;
                af[mi][0] = __float_as_uint(cA[r * 36 + c]);
                af[mi][1] = __float_as_uint(cA[(r + 8) * 36 + c]);
                af[mi][2] = __float_as_uint(cA[r * 36 + c + 4]);
                af[mi][3] = __float_as_uint(cA[(r + 8) * 36 + c + 4]);
            }
            #pragma unroll
            for (int ni = 0; ni < 4; ni++) {
                int cc = wn + ni * 8 + gr;
                bf[ni][0] = __float_as_uint(cB[cc * 36 + k0 + gq]);
                bf[ni][1] = __float_as_uint(cB[cc * 36 + k0 + 4 + gq]);
            }
            #pragma unroll
            for (int mi = 0; mi < 2; mi++)
                #pragma unroll
                for (int ni = 0; ni < 4; ni++)
                    MMA_TF32(acc[mi][ni], af[mi], bf[ni][0], bf[ni][1]);
        }
        __syncthreads();
    }

    #pragma unroll
    for (int mi = 0; mi < 2; mi++) {
        #pragma unroll
        for (int ni = 0; ni < 4; ni++) {
            int r = m0 + wm + mi * 16 + gr;
            int c = n0 + wn + ni * 8 + 2 * gq;
            float2 bb = *(const float2*)(bias + c);
            float v0 = acc[mi][ni][0] + bb.x, v1 = acc[mi][ni][1] + bb.y;
            float v2 = acc[mi][ni][2] + bb.x, v3 = acc[mi][ni][3] + bb.y;
            if (doRelu) {
                v0 = fmaxf(v0, 0.f); v1 = fmaxf(v1, 0.f);
                v2 = fmaxf(v2, 0.f); v3 = fmaxf(v3, 0.f);
            }
            if (resid) {
                float2 r0v = *(const float2*)(resid + (size_t)r * N + c);
                float2 r1v = *(const float2*)(resid + (size_t)(r + 8) * N + c);
                v0 += r0v.x; v1 += r0v.y; v2 += r1v.x; v3 += r1v.y;
            }
            *(float2*)(C + (size_t)r * N + c) = make_float2(v0, v1);
            *(float2*)(C + (size_t)(r + 8) * N + c) = make_float2(v2, v3);
        }
    }
}

// ---------------- attention smem geometry ----------------
#define KVS   40                       // K/V row stride (floats): conflict-free PV bf
#define PSS   68                       // P row stride
#define KVST  (2 * 64 * KVS)           // one stage: K tile + V tile
#define SM_PS (2 * KVST)               // offset of Ps (after 2 stages)

// K/V async loader: 64 rows x 32 cols each
__device__ __forceinline__ void attn_load(const float* __restrict__ kbase,
                                          const float* __restrict__ vbase,
                                          float* stage, int tid)
{
    float* sK = stage;
    float* sV = stage + 64 * KVS;
    #pragma unroll
    for (int i = 0; i < 4; i++) {
        int idx = tid + i * 128;
        int row = idx >> 3, c4 = (idx & 7) << 2;
        cp16(sK + row * KVS + c4, kbase + (size_t)row * NQKV + c4);
        cp16(sV + row * KVS + c4, vbase + (size_t)row * NQKV + c4);
    }
    CP_COMMIT();
}

// ---------------- tf32 flash attention: 128 q-rows/block, 4 warps ----------------
// Warp w owns rows [w*32, w*32+32): two 16-row m-tiles. Q frags in registers.
__global__ __launch_bounds__(128)
void attn_tc(const float* __restrict__ qkv, const float* __restrict__ dist,
             const float* __restrict__ tau, float* __restrict__ ctx)
{
    extern __shared__ float sm[];
    float* Ps = sm + SM_PS;             // 128 x PSS (aliases Q staging)

    int b = blockIdx.z, h = blockIdx.y, i0 = blockIdx.x * 128;
    int tid = threadIdx.x, lane = tid & 31, w = tid >> 5;
    int gr = lane >> 2, gq = lane & 3;
    int wr = w * 32;                    // warp's first row in tile

    const float sc = 0.17677669529663687f;  // 1/sqrt(32)

    // ---- stage Q (scaled) into Ps-alias smem, then lift fragments to registers
    {
        int r0 = tid >> 3, c = (tid & 7) * 4;
        #pragma unroll
        for (int i = 0; i < 8; i++) {
            int row = r0 + 16 * i;
            float4 q = *(const float4*)(qkv + (size_t)(b * NSEQ + i0 + row) * NQKV + h * 32 + c);
            Ps[row * 36 + c]     = __uint_as_float(f2tf(q.x * sc));
            Ps[row * 36 + c + 1] = __uint_as_float(f2tf(q.y * sc));
            Ps[row * 36 + c + 2] = __uint_as_float(f2tf(q.z * sc));
            Ps[row * 36 + c + 3] = __uint_as_float(f2tf(q.w * sc));
        }
    }
    __syncthreads();
    unsigned qf[2][4][4];               // [m-tile][k-chunk][frag]
    #pragma unroll
    for (int mt = 0; mt < 2; mt++) {
        int r = wr + mt * 16 + gr;
        #pragma unroll
        for (int k8 = 0; k8 < 4; k8++) {
            int c = k8 * 8 + gq;
            qf[mt][k8][0] = __float_as_uint(Ps[r * 36 + c]);
            qf[mt][k8][1] = __float_as_uint(Ps[(r + 8) * 36 + c]);
            qf[mt][k8][2] = __float_as_uint(Ps[r * 36 + c + 4]);
            qf[mt][k8][3] = __float_as_uint(Ps[(r + 8) * 36 + c + 4]);
        }
    }
    __syncthreads();

    const float* kbase = qkv + (size_t)(b * NSEQ) * NQKV + 256 + h * 32;
    const float* vbase = qkv + (size_t)(b * NSEQ) * NQKV + 512 + h * 32;
    attn_load(kbase, vbase, sm, tid);

    // per-thread row sets: 0: wr+gr, 1: wr+gr+8, 2: wr+gr+16, 3: wr+gr+24
    float tv[4];
    const float* dp[4];
    #pragma unroll
    for (int rs = 0; rs < 4; rs++) {
        int row = i0 + wr + rs * 8 + gr;
        tv[rs] = tau[((size_t)b * NH + h) * NSEQ + row];
        dp[rs] = dist + ((size_t)b * NSEQ + row) * NSEQ;
    }

    float mrow[4] = {-1e30f, -1e30f, -1e30f, -1e30f};
    float lrow[4] = {0.f, 0.f, 0.f, 0.f};
    float o[2][4][4];
    #pragma unroll
    for (int mt = 0; mt < 2; mt++)
        #pragma unroll
        for (int ni = 0; ni < 4; ni++)
            #pragma unroll
            for (int k = 0; k < 4; k++) o[mt][ni][k] = 0.f;

    for (int jt = 0; jt < NSEQ / 64; jt++) {
        float* cur = sm + (jt & 1) * KVST;
        float* nxt = sm + ((jt + 1) & 1) * KVST;
        if (jt + 1 < NSEQ / 64) {
            attn_load(kbase + (size_t)(jt + 1) * 64 * NQKV,
                      vbase + (size_t)(jt + 1) * 64 * NQKV, nxt, tid);
            asm volatile("cp.async.wait_group 1;");
        } else {
            asm volatile("cp.async.wait_group 0;");
        }
        __syncthreads();
        const float* Ks = cur;
        const float* Vs = cur + 64 * KVS;
        int j0 = jt * 64;

        // ---- S = Q @ K^T : 2 m-tiles x 8 n-tiles
        float s[2][8][4];
        #pragma unroll
        for (int mt = 0; mt < 2; mt++)
            #pragma unroll
            for (int ni = 0; ni < 8; ni++)
                #pragma unroll
                for (int k = 0; k < 4; k++) s[mt][ni][k] = 0.f;

        #pragma unroll
        for (int k8 = 0; k8 < 4; k8++) {
            int c = k8 * 8 + gq;
            unsigned bf[8][2];
            #pragma unroll
            for (int ni = 0; ni < 8; ni++) {
                int jj = ni * 8 + gr;
                bf[ni][0] = __float_as_uint(Ks[jj * KVS + c]);
                bf[ni][1] = __float_as_uint(Ks[jj * KVS + c + 4]);
            }
            #pragma unroll
            for (int mt = 0; mt < 2; mt++)
                #pragma unroll
                for (int ni = 0; ni < 8; ni++)
                    MMA_TF32(s[mt][ni], qf[mt][k8], bf[ni][0], bf[ni][1]);
        }

        // ---- bias + online softmax (4 row sets)
        float tm[4] = {-1e30f, -1e30f, -1e30f, -1e30f};
        #pragma unroll
        for (int mt = 0; mt < 2; mt++) {
            #pragma unroll
            for (int ni = 0; ni < 8; ni++) {
                int jc = j0 + ni * 8 + 2 * gq;
                float2 dA = *(const float2*)(dp[2 * mt] + jc);
                float2 dB = *(const float2*)(dp[2 * mt + 1] + jc);
                s[mt][ni][0] += dA.x * tv[2 * mt];
                s[mt][ni][1] += dA.y * tv[2 * mt];
                s[mt][ni][2] += dB.x * tv[2 * mt + 1];
                s[mt][ni][3] += dB.y * tv[2 * mt + 1];
                tm[2 * mt]     = fmaxf(tm[2 * mt],     fmaxf(s[mt][ni][0], s[mt][ni][1]));
                tm[2 * mt + 1] = fmaxf(tm[2 * mt + 1], fmaxf(s[mt][ni][2], s[mt][ni][3]));
            }
        }
        float cor[4];
        #pragma unroll
        for (int rs = 0; rs < 4; rs++) {
            tm[rs] = fmaxf(tm[rs], __shfl_xor_sync(0xffffffffu, tm[rs], 1));
            tm[rs] = fmaxf(tm[rs], __shfl_xor_sync(0xffffffffu, tm[rs], 2));
            float mn = fmaxf(mrow[rs], tm[rs]);
            cor[rs] = __expf(mrow[rs] - mn);
            mrow[rs] = mn;
        }
        float ps[4] = {0.f, 0.f, 0.f, 0.f};
        #pragma unroll
        for (int mt = 0; mt < 2; mt++) {
            #pragma unroll
            for (int ni = 0; ni < 8; ni++) {
                s[mt][ni][0] = __expf(s[mt][ni][0] - mrow[2 * mt]);
                s[mt][ni][1] = __expf(s[mt][ni][1] - mrow[2 * mt]);
                s[mt][ni][2] = __expf(s[mt][ni][2] - mrow[2 * mt + 1]);
                s[mt][ni][3] = __expf(s[mt][ni][3] - mrow[2 * mt + 1]);
                ps[2 * mt]     += s[mt][ni][0] + s[mt][ni][1];
                ps[2 * mt + 1] += s[mt][ni][2] + s[mt][ni][3];
            }
        }
        #pragma unroll
        for (int rs = 0; rs < 4; rs++) {
            ps[rs] += __shfl_xor_sync(0xffffffffu, ps[rs], 1);
            ps[rs] += __shfl_xor_sync(0xffffffffu, ps[rs], 2);
            lrow[rs] = lrow[rs] * cor[rs] + ps[rs];
        }
        #pragma unroll
        for (int mt = 0; mt < 2; mt++)
            #pragma unroll
            for (int ni = 0; ni < 4; ni++) {
                o[mt][ni][0] *= cor[2 * mt];     o[mt][ni][1] *= cor[2 * mt];
                o[mt][ni][2] *= cor[2 * mt + 1]; o[mt][ni][3] *= cor[2 * mt + 1];
            }

        // ---- stage P into warp-private smem strip
        #pragma unroll
        for (int mt = 0; mt < 2; mt++) {
            int rA = wr + mt * 16 + gr, rB = rA + 8;
            #pragma unroll
            for (int ni = 0; ni < 8; ni++) {
                int jc = ni * 8 + 2 * gq;
                Ps[rA * PSS + jc]     = s[mt][ni][0];
                Ps[rA * PSS + jc + 1] = s[mt][ni][1];
                Ps[rB * PSS + jc]     = s[mt][ni][2];
                Ps[rB * PSS + jc + 1] = s[mt][ni][3];
            }
        }
        __syncwarp();

        // ---- O += P @ V
        #pragma unroll
        for (int k8 = 0; k8 < 8; k8++) {
            int c = k8 * 8 + gq;
            unsigned af[2][4], bf[4][2];
            #pragma unroll
            for (int mt = 0; mt < 2; mt++) {
                int r = wr + mt * 16 + gr;
                af[mt][0] = __float_as_uint(Ps[r * PSS + c]);
                af[mt][1] = __float_as_uint(Ps[(r + 8) * PSS + c]);
                af[mt][2] = __float_as_uint(Ps[r * PSS + c + 4]);
                af[mt][3] = __float_as_uint(Ps[(r + 8) * PSS + c + 4]);
            }
            #pragma unroll
            for (int ni = 0; ni < 4; ni++) {
                bf[ni][0] = __float_as_uint(Vs[c * KVS + ni * 8 + gr]);
                bf[ni][1] = __float_as_uint(Vs[(c + 4) * KVS + ni * 8 + gr]);
            }
            #pragma unroll
            for (int mt = 0; mt < 2; mt++)
                #pragma unroll
                for (int ni = 0; ni < 4; ni++)
                    MMA_TF32(o[mt][ni], af[mt], bf[ni][0], bf[ni][1]);
        }
        __syncthreads();
    }

    // ---- write O / l
    float il[4];
    #pragma unroll
    for (int rs = 0; rs < 4; rs++) il[rs] = 1.f / lrow[rs];
    #pragma unroll
    for (int mt = 0; mt < 2; mt++) {
        size_t gA = (size_t)(b * NSEQ + i0 + wr + mt * 16 + gr) * 256;
        size_t gB = gA + (size_t)8 * 256;
        #pragma unroll
        for (int ni = 0; ni < 4; ni++) {
            int dcol = h * 32 + ni * 8 + 2 * gq;
            *(float2*)(ctx + gA + dcol) =
                make_float2(o[mt][ni][0] * il[2 * mt], o[mt][ni][1] * il[2 * mt]);
            *(float2*)(ctx + gB + dcol) =
                make_float2(o[mt][ni][2] * il[2 * mt + 1], o[mt][ni][3] * il[2 * mt + 1]);
        }
    }
}

// ---------------- row LayerNorm ----------------
__global__ void ln_kernel(const float* __restrict__ in, const float* __restrict__ g,
                          const float* __restrict__ bt, float* __restrict__ out)
{
    int row = blockIdx.x, t = threadIdx.x;
    float v = in[(size_t)row * DM + t];
    float s = v, s2 = v * v;
    #pragma unroll
    for (int o = 16; o > 0; o >>= 1) {
        s  += __shfl_xor_sync(0xffffffffu, s, o);
        s2 += __shfl_xor_sync(0xffffffffu, s2, o);
    }
    __shared__ float rs[8], rs2[8];
    __shared__ float mu_s, rstd_s;
    int w = t >> 5, lane = t & 31;
    if (lane == 0) { rs[w] = s; rs2[w] = s2; }
    __syncthreads();
    if (t == 0) {
        float a = 0.f, b2 = 0.f;
        #pragma unroll
        for (int i = 0; i < 8; i++) { a += rs[i]; b2 += rs2[i]; }
        float mu = a * (1.f / 256.f);
        float var = b2 * (1.f / 256.f) - mu * mu;
        mu_s = mu;
        rstd_s = rsqrtf(var + 1e-5f);
    }
    __syncthreads();
    out[(size_t)row * DM + t] = (v - mu_s) * rstd_s * g[t] + bt[t];
}

// ---------------- launch ----------------
static float* sym_addr(const void* sym)
{
    void* p = nullptr;
    cudaGetSymbolAddress(&p, sym);
    return (float*)p;
}

extern "C" void kernel_launch(void* const* d_in, const int* in_sizes, int n_in,
                              void* d_out, int out_size)
{
    const float* embed = (const float*)d_in[0];
    const float* dist  = (const float*)d_in[2];
    const float* qpos  = (const float*)d_in[3];
    const float* inw   = (const float*)d_in[4];
    const float* inb   = (const float*)d_in[5];
    const float* outw  = (const float*)d_in[6];
    const float* outb  = (const float*)d_in[7];
    const float* tauw  = (const float*)d_in[8];
    const float* taub  = (const float*)d_in[9];
    const float* w1    = (const float*)d_in[10];
    const float* b1    = (const float*)d_in[11];
    const float* w2    = (const float*)d_in[12];
    const float* b2    = (const float*)d_in[13];
    const float* g1    = (const float*)d_in[14];
    const float* be1   = (const float*)d_in[15];
    const float* g2    = (const float*)d_in[16];
    const float* be2   = (const float*)d_in[17];
    float* out = (float*)d_out;

    float* qkin = sym_addr(g_qkin);
    float* qkv  = sym_addr(g_qkv);
    float* tau  = sym_addr(g_tau);
    float* ctx  = sym_addr(g_ctx);
    float* y    = sym_addr(g_y);
    float* x    = sym_addr(g_x);
    float* hbuf = sym_addr(g_h);

    const int smem128 = 2 * (128 + 64) * 36 * 4;            // 55296
    const int smem64  = 2 * (64 + 64) * 36 * 4;             // 36864
    const int smemAtt = (SM_PS + 128 * PSS) * 4;            // 2 KV stages + Ps

    cudaFuncSetAttribute(gemm_tc<128>, cudaFuncAttributeMaxDynamicSharedMemorySize, smem128);
    cudaFuncSetAttribute(gemm_tc<64>,  cudaFuncAttributeMaxDynamicSharedMemorySize, smem64);
    cudaFuncSetAttribute(attn_tc,      cudaFuncAttributeMaxDynamicSharedMemorySize, smemAtt);

    // 1) qk = embed + query_pos
    add_pos_kernel<<<(MROWS * DM / 4) / 256, 256>>>(
        (const float4*)embed, (const float4*)qpos, (float4*)qkin);

    // 2) tau
    tau_kernel<<<512, 256>>>(embed, tauw, taub, tau);

    // 3) fused QKV projection
    gemm_tc<128><<<dim3(NQKV / 64, MROWS / 128), 256, smem128>>>(
        qkin, embed, inw, inb, nullptr, qkv, MROWS, NQKV, DM, 0, 512);

    // 4) attention (128 q-rows per block)
    attn_tc<<<dim3(NSEQ / 128, NH, BD), 128, smemAtt>>>(qkv, dist, tau, ctx);

    // 5) out projection + residual(embed)
    gemm_tc<64><<<dim3(DM / 64, MROWS / 64), 128, smem64>>>(
        ctx, ctx, outw, outb, embed, y, MROWS, DM, DM, 0, 1 << 30);

    // 6) LN1
    ln_kernel<<<MROWS, 256>>>(y, g1, be1, x);

    // 7) FFN1 + ReLU
    gemm_tc<128><<<dim3(DFFN / 64, MROWS / 128), 256, smem128>>>(
        x, x, w1, b1, nullptr, hbuf, MROWS, DFFN, DM, 1, 1 << 30);

    // 8) FFN2 + residual(x)
    gemm_tc<64><<<dim3(DM / 64, MROWS / 64), 128, smem64>>>(
        hbuf, hbuf, w2, b2, x, y, MROWS, DM, DFFN, 0, 1 << 30);

    // 9) LN2 -> out
    ln_kernel<<<MROWS, 256>>>(y, g2, be2, out);
}

// round 8
// speedup vs baseline: 1.0495x; 1.0495x over previous
#include <cuda_runtime.h>
#include <stdint.h>
#include <math.h>

#define BD    4
#define NSEQ  1024
#define DM    256
#define NH    8
#define HD    32
#define DFFN  1024
#define MROWS (BD * NSEQ)   // 4096
#define NQKV  768

// ---------------- static scratch ----------------
__device__ float g_qkin[MROWS * DM];        // embed + query_pos
__device__ float g_qkv[MROWS * NQKV];       // [4096, 768]: q | k | v
__device__ float g_tau[BD * NH * NSEQ];     // [B, H, N]
__device__ float g_ctx[MROWS * DM];
__device__ float g_y[MROWS * DM];
__device__ float g_x[MROWS * DM];
__device__ float g_h[MROWS * DFFN];

// ---------------- helpers ----------------
__device__ __forceinline__ unsigned f2tf(float f)
{
    unsigned u;
    asm("cvt.rna.tf32.f32 %0, %1;" : "=r"(u) : "f"(f));
    return u;
}

__device__ __forceinline__ void cp16(float* dst, const float* src)
{
    unsigned d = (unsigned)__cvta_generic_to_shared(dst);
    asm volatile("cp.async.cg.shared.global [%0], [%1], 16;" :: "r"(d), "l"(src));
}

#define CP_COMMIT() asm volatile("cp.async.commit_group;")

#define MMA_TF32(d, a, b0, b1)                                              \
    asm volatile("mma.sync.aligned.m16n8k8.row.col.f32.tf32.tf32.f32 "      \
                 "{%0,%1,%2,%3}, {%4,%5,%6,%7}, {%8,%9}, {%0,%1,%2,%3};"    \
                 : "+f"((d)[0]), "+f"((d)[1]), "+f"((d)[2]), "+f"((d)[3])   \
                 : "r"((a)[0]), "r"((a)[1]), "r"((a)[2]), "r"((a)[3]),      \
                   "r"(b0), "r"(b1))

// ---------------- elementwise: qk = embed + query_pos ----------------
__global__ void add_pos_kernel(const float4* __restrict__ a,
                               const float4* __restrict__ b,
                               float4* __restrict__ o)
{
    int i = blockIdx.x * blockDim.x + threadIdx.x;
    float4 x = a[i], y = b[i];
    o[i] = make_float4(x.x + y.x, x.y + y.y, x.z + y.z, x.w + y.w);
}

// ---------------- tau ----------------
__global__ void tau_kernel(const float* __restrict__ embed,
                           const float* __restrict__ tw,
                           const float* __restrict__ tb,
                           float* __restrict__ tau)
{
    int warp_id = (blockIdx.x * blockDim.x + threadIdx.x) >> 5;
    int lane = threadIdx.x & 31;
    const float* er = embed + (size_t)warp_id * DM;
    float ph[NH];
    #pragma unroll
    for (int h = 0; h < NH; h++) ph[h] = 0.f;
    #pragma unroll
    for (int t = 0; t < 8; t++) {
        int d = lane + t * 32;
        float e = er[d];
        #pragma unroll
        for (int h = 0; h < NH; h++) ph[h] += e * tw[h * DM + d];
    }
    #pragma unroll
    for (int h = 0; h < NH; h++) {
        float v = ph[h];
        #pragma unroll
        for (int o = 16; o > 0; o >>= 1) v += __shfl_xor_sync(0xffffffffu, v, o);
        if (lane == 0) {
            int b = warp_id >> 10, n = warp_id & 1023;
            tau[((size_t)b * NH + h) * NSEQ + n] = v + tb[h];
        }
    }
}

// ---------------- async tile loader for GEMM ----------------
template<int BM>
__device__ __forceinline__ void gemm_load(const float* __restrict__ Ag,
                                          const float* __restrict__ Wg,
                                          float* sA, float* sB, int tid, int K)
{
    constexpr int T = BM * 2;
    #pragma unroll
    for (int i = 0; i < (BM * 8) / T; i++) {
        int idx = tid + i * T;
        int row = idx >> 3, c4 = (idx & 7) << 2;
        cp16(sA + row * 36 + c4, Ag + (size_t)row * K + c4);
    }
    #pragma unroll
    for (int i = 0; i < 512 / T; i++) {
        int idx = tid + i * T;
        int row = idx >> 3, c4 = (idx & 7) << 2;
        cp16(sB + row * 36 + c4, Wg + (size_t)row * K + c4);
    }
    CP_COMMIT();
}

// ---------------- tf32 tensor-core GEMM (double-buffered cp.async) ----------------
template<int BM>
__global__ void gemm_tc(const float* __restrict__ A, const float* __restrict__ A2,
                        const float* __restrict__ W, const float* __restrict__ bias,
                        const float* __restrict__ resid, float* __restrict__ C,
                        int M, int N, int K, int doRelu, int nsplit)
{
    extern __shared__ float smem[];
    constexpr int STAGE = (BM + 64) * 36;
    int tid = threadIdx.x, lane = tid & 31, wid = tid >> 5;
    int m0 = blockIdx.y * BM, n0 = blockIdx.x * 64;
    const float* Ause = (n0 >= nsplit) ? A2 : A;
    const float* Abase = Ause + (size_t)m0 * K;
    const float* Wbase = W + (size_t)n0 * K;
    int nk = K >> 5;

    constexpr int WMN = BM / 32;
    int wm = (wid % WMN) * 32, wn = (wid / WMN) * 32;
    int gr = lane >> 2, gq = lane & 3;

    gemm_load<BM>(Abase, Wbase, smem, smem + BM * 36, tid, K);

    float acc[2][4][4];
    #pragma unroll
    for (int mi = 0; mi < 2; mi++)
        #pragma unroll
        for (int ni = 0; ni < 4; ni++)
            #pragma unroll
            for (int k = 0; k < 4; k++) acc[mi][ni][k] = 0.f;

    for (int kt = 0; kt < nk; kt++) {
        float* cur = smem + (kt & 1) * STAGE;
        float* nxt = smem + ((kt + 1) & 1) * STAGE;
        if (kt + 1 < nk) {
            gemm_load<BM>(Abase + (kt + 1) * 32, Wbase + (kt + 1) * 32,
                          nxt, nxt + BM * 36, tid, K);
            asm volatile("cp.async.wait_group 1;");
        } else {
            asm volatile("cp.async.wait_group 0;");
        }
        __syncthreads();
        const float* cA = cur;
        const float* cB = cur + BM * 36;
        #pragma unroll
        for (int k0 = 0; k0 < 32; k0 += 8) {
            unsigned af[2][4], bf[4][2];
            #pragma unroll
            for (int mi = 0; mi < 2; mi++) {
                int r = wm + mi * 16 + gr, c = k0 + gq;
                af[mi][0] = __float_as_uint(cA[r * 36 + c]);
                af[mi][1] = __float_as_uint(cA[(r + 8) * 36 + c]);
                af[mi][2] = __float_as_uint(cA[r * 36 + c + 4]);
                af[mi][3] = __float_as_uint(cA[(r + 8) * 36 + c + 4]);
            }
            #pragma unroll
            for (int ni = 0; ni < 4; ni++) {
                int cc = wn + ni * 8 + gr;
                bf[ni][0] = __float_as_uint(cB[cc * 36 + k0 + gq]);
                bf[ni][1] = __float_as_uint(cB[cc * 36 + k0 + 4 + gq]);
            }
            #pragma unroll
            for (int mi = 0; mi < 2; mi++)
                #pragma unroll
                for (int ni = 0; ni < 4; ni++)
                    MMA_TF32(acc[mi][ni], af[mi], bf[ni][0], bf[ni][1]);
        }
        __syncthreads();
    }

    #pragma unroll
    for (int mi = 0; mi < 2; mi++) {
        #pragma unroll
        for (int ni = 0; ni < 4; ni++) {
            int r = m0 + wm + mi * 16 + gr;
            int c = n0 + wn + ni * 8 + 2 * gq;
            float2 bb = *(const float2*)(bias + c);
            float v0 = acc[mi][ni][0] + bb.x, v1 = acc[mi][ni][1] + bb.y;
            float v2 = acc[mi][ni][2] + bb.x, v3 = acc[mi][ni][3] + bb.y;
            if (doRelu) {
                v0 = fmaxf(v0, 0.f); v1 = fmaxf(v1, 0.f);
                v2 = fmaxf(v2, 0.f); v3 = fmaxf(v3, 0.f);
            }
            if (resid) {
                float2 r0v = *(const float2*)(resid + (size_t)r * N + c);
                float2 r1v = *(const float2*)(resid + (size_t)(r + 8) * N + c);
                v0 += r0v.x; v1 += r0v.y; v2 += r1v.x; v3 += r1v.y;
            }
            *(float2*)(C + (size_t)r * N + c) = make_float2(v0, v1);
            *(float2*)(C + (size_t)(r + 8) * N + c) = make_float2(v2, v3);
        }
    }
}

// ---------------- attention smem geometry ----------------
#define KVS   40                        // K/V row stride: conflict-free B-frag loads
#define QSS   36                        // Q staging row stride (32 cols + pad)
#define PPS   68                        // P row stride (64 cols + pad)
#define KVST  (2 * 64 * KVS)            // one stage (K+V) = 5120 floats
#define OFF_STAT (2 * KVST)             // pmax[2][64], psum[2][64]
#define OFF_PS   (OFF_STAT + 256)       // 64 x PPS (aliases Q staging / Osum)
#define SMEM_ATT ((OFF_PS + 64 * PPS) * 4)

// K/V async loader: 64 rows x 32 floats each, 256 threads
__device__ __forceinline__ void attn_load(const float* __restrict__ kbase,
                                          const float* __restrict__ vbase,
                                          float* stage, int tid)
{
    float* sK = stage;
    float* sV = stage + 64 * KVS;
    #pragma unroll
    for (int i = 0; i < 2; i++) {
        int idx = tid + i * 256;
        int row = idx >> 3, c4 = (idx & 7) << 2;
        cp16(sK + row * KVS + c4, kbase + (size_t)row * NQKV + c4);
        cp16(sV + row * KVS + c4, vbase + (size_t)row * NQKV + c4);
    }
    CP_COMMIT();
}

// ---------------- tf32 flash attention: 64 q-rows, 8 warps (4m x 2n) ----------------
__global__ __launch_bounds__(256, 3)
void attn_tc(const float* __restrict__ qkv, const float* __restrict__ dist,
             const float* __restrict__ tau, float* __restrict__ ctx)
{
    extern __shared__ float sm[];
    float* pmax = sm + OFF_STAT;        // [2][64]
    float* psum = pmax + 128;           // [2][64]
    float* Ps   = sm + OFF_PS;          // 64 x PPS

    int b = blockIdx.z, h = blockIdx.y, i0 = blockIdx.x * 64;
    int tid = threadIdx.x, lane = tid & 31, wid = tid >> 5;
    int wm = wid & 3, wn = wid >> 2;
    int gr = lane >> 2, gq = lane & 3;
    int wr = wm * 16;

    const float sc = 0.17677669529663687f;  // 1/sqrt(32)

    // ---- stage Q (scaled, tf32) at stride QSS inside Ps buffer, lift A-frags
    #pragma unroll
    for (int i = 0; i < 2; i++) {
        int idx = tid + i * 256;
        int row = idx >> 3, c = (idx & 7) << 2;
        float4 q = *(const float4*)(qkv + (size_t)(b * NSEQ + i0 + row) * NQKV + h * 32 + c);
        Ps[row * QSS + c]     = __uint_as_float(f2tf(q.x * sc));
        Ps[row * QSS + c + 1] = __uint_as_float(f2tf(q.y * sc));
        Ps[row * QSS + c + 2] = __uint_as_float(f2tf(q.z * sc));
        Ps[row * QSS + c + 3] = __uint_as_float(f2tf(q.w * sc));
    }
    __syncthreads();
    unsigned qf[4][4];
    #pragma unroll
    for (int k8 = 0; k8 < 4; k8++) {
        int c = k8 * 8 + gq;
        qf[k8][0] = __float_as_uint(Ps[(wr + gr) * QSS + c]);
        qf[k8][1] = __float_as_uint(Ps[(wr + 8 + gr) * QSS + c]);
        qf[k8][2] = __float_as_uint(Ps[(wr + gr) * QSS + c + 4]);
        qf[k8][3] = __float_as_uint(Ps[(wr + 8 + gr) * QSS + c + 4]);
    }
    __syncthreads();

    const float* kbase = qkv + (size_t)(b * NSEQ) * NQKV + 256 + h * 32;
    const float* vbase = qkv + (size_t)(b * NSEQ) * NQKV + 512 + h * 32;
    attn_load(kbase, vbase, sm, tid);

    int r0 = wr + gr, r1 = wr + 8 + gr;
    float tv0 = tau[((size_t)b * NH + h) * NSEQ + i0 + r0];
    float tv1 = tau[((size_t)b * NH + h) * NSEQ + i0 + r1];
    const float* dp0 = dist + ((size_t)b * NSEQ + i0 + r0) * NSEQ + wn * 32;
    const float* dp1 = dist + ((size_t)b * NSEQ + i0 + r1) * NSEQ + wn * 32;

    float mr0 = -1e30f, mr1 = -1e30f, lr0 = 0.f, lr1 = 0.f;
    float o[4][4];
    #pragma unroll
    for (int ni = 0; ni < 4; ni++)
        #pragma unroll
        for (int k = 0; k < 4; k++) o[ni][k] = 0.f;

    for (int jt = 0; jt < NSEQ / 64; jt++) {
        float* cur = sm + (jt & 1) * KVST;
        float* nxt = sm + ((jt + 1) & 1) * KVST;
        if (jt + 1 < NSEQ / 64) {
            attn_load(kbase + (size_t)(jt + 1) * 64 * NQKV,
                      vbase + (size_t)(jt + 1) * 64 * NQKV, nxt, tid);
            asm volatile("cp.async.wait_group 1;");
        } else {
            asm volatile("cp.async.wait_group 0;");
        }
        __syncthreads();                               // [S1] KV visible
        const float* Ks = cur;
        const float* Vs = cur + 64 * KVS;

        // ---- S quadrant: rows wr.., cols wn*32 + ni*8
        float s[4][4];
        #pragma unroll
        for (int ni = 0; ni < 4; ni++)
            #pragma unroll
            for (int k = 0; k < 4; k++) s[ni][k] = 0.f;

        #pragma unroll
        for (int k8 = 0; k8 < 4; k8++) {
            int c = k8 * 8 + gq;
            unsigned bf[4][2];
            #pragma unroll
            for (int ni = 0; ni < 4; ni++) {
                int jj = wn * 32 + ni * 8 + gr;
                bf[ni][0] = __float_as_uint(Ks[jj * KVS + c]);
                bf[ni][1] = __float_as_uint(Ks[jj * KVS + c + 4]);
            }
            #pragma unroll
            for (int ni = 0; ni < 4; ni++)
                MMA_TF32(s[ni], qf[k8], bf[ni][0], bf[ni][1]);
        }

        // ---- bias + partial max
        float tm0 = -1e30f, tm1 = -1e30f;
        #pragma unroll
        for (int ni = 0; ni < 4; ni++) {
            int jc = jt * 64 + ni * 8 + 2 * gq;        // dp already offset by wn*32
            float2 dA = *(const float2*)(dp0 + jc);
            float2 dB = *(const float2*)(dp1 + jc);
            s[ni][0] += dA.x * tv0;
            s[ni][1] += dA.y * tv0;
            s[ni][2] += dB.x * tv1;
            s[ni][3] += dB.y * tv1;
            tm0 = fmaxf(tm0, fmaxf(s[ni][0], s[ni][1]));
            tm1 = fmaxf(tm1, fmaxf(s[ni][2], s[ni][3]));
        }
        tm0 = fmaxf(tm0, __shfl_xor_sync(0xffffffffu, tm0, 1));
        tm0 = fmaxf(tm0, __shfl_xor_sync(0xffffffffu, tm0, 2));
        tm1 = fmaxf(tm1, __shfl_xor_sync(0xffffffffu, tm1, 1));
        tm1 = fmaxf(tm1, __shfl_xor_sync(0xffffffffu, tm1, 2));
        if (gq == 0) {
            pmax[wn * 64 + r0] = tm0;
            pmax[wn * 64 + r1] = tm1;
        }
        __syncthreads();                               // [S2] stats half 1

        float mn0 = fmaxf(mr0, fmaxf(pmax[r0], pmax[64 + r0]));
        float mn1 = fmaxf(mr1, fmaxf(pmax[r1], pmax[64 + r1]));
        float cor0 = __expf(mr0 - mn0), cor1 = __expf(mr1 - mn1);
        mr0 = mn0; mr1 = mn1;

        float ps0 = 0.f, ps1 = 0.f;
        #pragma unroll
        for (int ni = 0; ni < 4; ni++) {
            s[ni][0] = __expf(s[ni][0] - mn0);
            s[ni][1] = __expf(s[ni][1] - mn0);
            s[ni][2] = __expf(s[ni][2] - mn1);
            s[ni][3] = __expf(s[ni][3] - mn1);
            ps0 += s[ni][0] + s[ni][1];
            ps1 += s[ni][2] + s[ni][3];
        }
        ps0 += __shfl_xor_sync(0xffffffffu, ps0, 1);
        ps0 += __shfl_xor_sync(0xffffffffu, ps0, 2);
        ps1 += __shfl_xor_sync(0xffffffffu, ps1, 1);
        ps1 += __shfl_xor_sync(0xffffffffu, ps1, 2);
        if (gq == 0) {
            psum[wn * 64 + r0] = ps0;
            psum[wn * 64 + r1] = ps1;
        }

        // ---- stage P strip (warp-private: rows wr.., cols wn*32..)
        #pragma unroll
        for (int ni = 0; ni < 4; ni++) {
            int jc = wn * 32 + ni * 8 + 2 * gq;
            Ps[r0 * PPS + jc]     = s[ni][0];
            Ps[r0 * PPS + jc + 1] = s[ni][1];
            Ps[r1 * PPS + jc]     = s[ni][2];
            Ps[r1 * PPS + jc + 1] = s[ni][3];
        }
        __syncthreads();                               // [S3] stats half 2 + P ordered

        lr0 = lr0 * cor0 + psum[r0] + psum[64 + r0];
        lr1 = lr1 * cor1 + psum[r1] + psum[64 + r1];
        #pragma unroll
        for (int ni = 0; ni < 4; ni++) {
            o[ni][0] *= cor0; o[ni][1] *= cor0;
            o[ni][2] *= cor1; o[ni][3] *= cor1;
        }

        // ---- partial O += P[:, wn-half] @ V[wn-half, :]
        #pragma unroll
        for (int k8 = 0; k8 < 4; k8++) {
            int c = (wn * 4 + k8) * 8 + gq;
            unsigned af[4], bf[4][2];
            af[0] = __float_as_uint(Ps[r0 * PPS + c]);
            af[1] = __float_as_uint(Ps[r1 * PPS + c]);
            af[2] = __float_as_uint(Ps[r0 * PPS + c + 4]);
            af[3] = __float_as_uint(Ps[r1 * PPS + c + 4]);
            #pragma unroll
            for (int ni = 0; ni < 4; ni++) {
                bf[ni][0] = __float_as_uint(Vs[c * KVS + ni * 8 + gr]);
                bf[ni][1] = __float_as_uint(Vs[(c + 4) * KVS + ni * 8 + gr]);
            }
            #pragma unroll
            for (int ni = 0; ni < 4; ni++)
                MMA_TF32(o[ni], af, bf[ni][0], bf[ni][1]);
        }
        __syncthreads();                               // [S4] protect cur
    }

    // ---- combine the two k-half partial Os via smem (alias Ps as Osum 64x33)
    float* Osum = Ps;
    if (wn == 0) {
        #pragma unroll
        for (int ni = 0; ni < 4; ni++) {
            int d = ni * 8 + 2 * gq;
            Osum[r0 * 33 + d]     = o[ni][0];
            Osum[r0 * 33 + d + 1] = o[ni][1];
            Osum[r1 * 33 + d]     = o[ni][2];
            Osum[r1 * 33 + d + 1] = o[ni][3];
        }
    }
    __syncthreads();
    if (wn == 1) {
        float il0 = 1.f / lr0, il1 = 1.f / lr1;
        size_t gA = (size_t)(b * NSEQ + i0 + r0) * 256 + h * 32;
        size_t gB = (size_t)(b * NSEQ + i0 + r1) * 256 + h * 32;
        #pragma unroll
        for (int ni = 0; ni < 4; ni++) {
            int d = ni * 8 + 2 * gq;
            float a0 = (Osum[r0 * 33 + d]     + o[ni][0]) * il0;
            float a1 = (Osum[r0 * 33 + d + 1] + o[ni][1]) * il0;
            float a2 = (Osum[r1 * 33 + d]     + o[ni][2]) * il1;
            float a3 = (Osum[r1 * 33 + d + 1] + o[ni][3]) * il1;
            *(float2*)(ctx + gA + d) = make_float2(a0, a1);
            *(float2*)(ctx + gB + d) = make_float2(a2, a3);
        }
    }
}

// ---------------- row LayerNorm ----------------
__global__ void ln_kernel(const float* __restrict__ in, const float* __restrict__ g,
                          const float* __restrict__ bt, float* __restrict__ out)
{
    int row = blockIdx.x, t = threadIdx.x;
    float v = in[(size_t)row * DM + t];
    float s = v, s2 = v * v;
    #pragma unroll
    for (int o = 16; o > 0; o >>= 1) {
        s  += __shfl_xor_sync(0xffffffffu, s, o);
        s2 += __shfl_xor_sync(0xffffffffu, s2, o);
    }
    __shared__ float rs[8], rs2[8];
    __shared__ float mu_s, rstd_s;
    int w = t >> 5, lane = t & 31;
    if (lane == 0) { rs[w] = s; rs2[w] = s2; }
    __syncthreads();
    if (t == 0) {
        float a = 0.f, b2 = 0.f;
        #pragma unroll
        for (int i = 0; i < 8; i++) { a += rs[i]; b2 += rs2[i]; }
        float mu = a * (1.f / 256.f);
        float var = b2 * (1.f / 256.f) - mu * mu;
        mu_s = mu;
        rstd_s = rsqrtf(var + 1e-5f);
    }
    __syncthreads();
    out[(size_t)row * DM + t] = (v - mu_s) * rstd_s * g[t] + bt[t];
}

// ---------------- launch ----------------
static float* sym_addr(const void* sym)
{
    void* p = nullptr;
    cudaGetSymbolAddress(&p, sym);
    return (float*)p;
}

extern "C" void kernel_launch(void* const* d_in, const int* in_sizes, int n_in,
                              void* d_out, int out_size)
{
    const float* embed = (const float*)d_in[0];
    const float* dist  = (const float*)d_in[2];
    const float* qpos  = (const float*)d_in[3];
    const float* inw   = (const float*)d_in[4];
    const float* inb   = (const float*)d_in[5];
    const float* outw  = (const float*)d_in[6];
    const float* outb  = (const float*)d_in[7];
    const float* tauw  = (const float*)d_in[8];
    const float* taub  = (const float*)d_in[9];
    const float* w1    = (const float*)d_in[10];
    const float* b1    = (const float*)d_in[11];
    const float* w2    = (const float*)d_in[12];
    const float* b2    = (const float*)d_in[13];
    const float* g1    = (const float*)d_in[14];
    const float* be1   = (const float*)d_in[15];
    const float* g2    = (const float*)d_in[16];
    const float* be2   = (const float*)d_in[17];
    float* out = (float*)d_out;

    float* qkin = sym_addr(g_qkin);
    float* qkv  = sym_addr(g_qkv);
    float* tau  = sym_addr(g_tau);
    float* ctx  = sym_addr(g_ctx);
    float* y    = sym_addr(g_y);
    float* x    = sym_addr(g_x);
    float* hbuf = sym_addr(g_h);

    const int smem128 = 2 * (128 + 64) * 36 * 4;   // 55296
    const int smem64  = 2 * (64 + 64) * 36 * 4;    // 36864

    cudaFuncSetAttribute(gemm_tc<128>, cudaFuncAttributeMaxDynamicSharedMemorySize, smem128);
    cudaFuncSetAttribute(gemm_tc<64>,  cudaFuncAttributeMaxDynamicSharedMemorySize, smem64);
    cudaFuncSetAttribute(attn_tc,      cudaFuncAttributeMaxDynamicSharedMemorySize, SMEM_ATT);

    // 1) qk = embed + query_pos
    add_pos_kernel<<<(MROWS * DM / 4) / 256, 256>>>(
        (const float4*)embed, (const float4*)qpos, (float4*)qkin);

    // 2) tau
    tau_kernel<<<512, 256>>>(embed, tauw, taub, tau);

    // 3) fused QKV projection
    gemm_tc<128><<<dim3(NQKV / 64, MROWS / 128), 256, smem128>>>(
        qkin, embed, inw, inb, nullptr, qkv, MROWS, NQKV, DM, 0, 512);

    // 4) attention (64 q-rows, 8 warps)
    attn_tc<<<dim3(NSEQ / 64, NH, BD), 256, SMEM_ATT>>>(qkv, dist, tau, ctx);

    // 5) out projection + residual(embed)
    gemm_tc<64><<<dim3(DM / 64, MROWS / 64), 128, smem64>>>(
        ctx, ctx, outw, outb, embed, y, MROWS, DM, DM, 0, 1 << 30);

    // 6) LN1
    ln_kernel<<<MROWS, 256>>>(y, g1, be1, x);

    // 7) FFN1 + ReLU
    gemm_tc<128><<<dim3(DFFN / 64, MROWS / 128), 256, smem128>>>(
        x, x, w1, b1, nullptr, hbuf, MROWS, DFFN, DM, 1, 1 << 30);

    // 8) FFN2 + residual(x)
    gemm_tc<64><<<dim3(DM / 64, MROWS / 64), 128, smem64>>>(
        hbuf, hbuf, w2, b2, x, y, MROWS, DM, DFFN, 0, 1 << 30);

    // 9) LN2 -> out
    ln_kernel<<<MROWS, 256>>>(y, g2, be2, out);
}